// round 5
// baseline (speedup 1.0000x reference)
#include <cuda_runtime.h>
#include <cstdint>

// ---------------- problem constants ----------------
#define G_    64
#define T_    8192
#define DIN_  2560
#define DOUT_ 1664
#define CAP_  256

// ---------------- tiling ----------------
#define BM 64
#define BN 256
#define BK 16
#define NK (DIN_ / BK)                 // 160
#define NT_N ((DOUT_ + BN - 1) / BN)   // 7 (last tile masked)

#define LDK  20                        // A row stride in words (80B)
#define LDBN 264                       // B row stride in words

#define A_WORDS (BM * LDK)             // 1280
#define B_WORDS (BK * LDBN)            // 4224
#define A_BYTES (A_WORDS * 4)          // 5120
#define STG_BYTES ((A_WORDS + B_WORDS) * 4)   // 22016
#define NSTAGE 3
#define SMEM_TOTAL (NSTAGE * STG_BYTES)       // 66048

__device__ int g_starts[G_];

__global__ void starts_kernel(const int* __restrict__ counts) {
    if (threadIdx.x == 0 && blockIdx.x == 0) {
        int s = 0;
        for (int g = 0; g < G_; ++g) { g_starts[g] = s; s += counts[g]; }
    }
}

static __device__ __forceinline__ uint32_t smem_u32(const void* p) {
    uint32_t a;
    asm("{ .reg .u64 t; cvta.to.shared.u64 t, %1; cvt.u32.u64 %0, t; }" : "=r"(a) : "l"(p));
    return a;
}

static __device__ __forceinline__ uint32_t f2tf32(uint32_t rawf) {
    uint32_t u;
    asm("cvt.rna.tf32.f32 %0, %1;" : "=r"(u) : "r"(rawf));
    return u;
}

static __device__ __forceinline__ void cp16(uint32_t dst, const void* src) {
    asm volatile("cp.async.cg.shared.global [%0], [%1], 16;" :: "r"(dst), "l"(src));
}
#define CP_COMMIT()   asm volatile("cp.async.commit_group;")
#define CP_WAIT(n)    asm volatile("cp.async.wait_group %0;" :: "n"(n) : "memory")

#define LDSM4(r, a) \
    asm volatile("ldmatrix.sync.aligned.m8n8.x4.shared.b16 {%0,%1,%2,%3}, [%4];" \
        : "=r"((r)[0]), "=r"((r)[1]), "=r"((r)[2]), "=r"((r)[3]) : "r"(a))

static __device__ __forceinline__ void mma_tf32(float* c, const uint32_t* a,
                                                uint32_t b0, uint32_t b1) {
    asm volatile(
        "mma.sync.aligned.m16n8k8.row.col.f32.tf32.tf32.f32 "
        "{%0,%1,%2,%3}, {%4,%5,%6,%7}, {%8,%9}, {%0,%1,%2,%3};\n"
        : "+f"(c[0]), "+f"(c[1]), "+f"(c[2]), "+f"(c[3])
        : "r"(a[0]), "r"(a[1]), "r"(a[2]), "r"(a[3]), "r"(b0), "r"(b1));
}

__global__ __launch_bounds__(256, 2)
void grouped_gemm_kernel(const float* __restrict__ X, const float* __restrict__ W,
                         const int* __restrict__ counts, float* __restrict__ Y) {
    extern __shared__ uint32_t smem[];   // [NSTAGE][A | B]

    const int g  = blockIdx.z;
    const int mt = blockIdx.y;
    const int nt = blockIdx.x;
    const int cnt = counts[g];
    if (mt * BM >= cnt) return;
    const int gstart = g_starts[g];

    const int t    = threadIdx.x;
    const int lane = t & 31;
    const int wid  = t >> 5;
    const int warpM = wid & 1;           // 2 warps along M (32 rows each)
    const int warpN = wid >> 1;          // 4 warps along N (64 cols each)
    const int m0 = warpM * 32;
    const int n0 = warpN * 64;
    const int tg  = lane >> 2;
    const int tig = lane & 3;

    // ---- cp.async mapping ----
    // A: 1 chunk/thread: row = t>>2 (0..63), kv = t&3
    const int a_row = t >> 2;
    const int a_kv  = t & 3;
    long long arow = (long long)gstart + mt * BM + a_row;
    if (arow > T_ - 1) arow = T_ - 1;    // clamp; masked in epilogue
    const float* Ag = X + arow * DIN_ + a_kv * 4;
    const uint32_t aDst = (uint32_t)(a_row * LDK + a_kv * 4) * 4;

    // B: 4 chunks/thread: k = (t>>6) + 4*i, nv = t&63
    const int b_k0 = t >> 6;             // 0..3
    const int b_nv = t & 63;
    int bcol = nt * BN + b_nv * 4;
    if (bcol > DOUT_ - 4) bcol = DOUT_ - 4;   // clamp tail tile
    const float* Bg = W + (long long)g * DIN_ * DOUT_ + bcol;
    const uint32_t bDstBase = (uint32_t)(b_k0 * LDBN + b_nv * 4) * 4;

    const uint32_t sBase = smem_u32(smem);

    auto issue_stage = [&](int kt) {
        const uint32_t stg = sBase + (uint32_t)((kt % NSTAGE) * STG_BYTES);
        const int k0 = kt * BK;
        cp16(stg + aDst, Ag + k0);
        #pragma unroll
        for (int i = 0; i < 4; ++i)
            cp16(stg + A_BYTES + bDstBase + (uint32_t)(4 * i * LDBN * 4),
                 Bg + (long long)(k0 + b_k0 + 4 * i) * DOUT_);
    };

    // ---- ldmatrix A addresses ----
    const int l15 = lane & 15;
    const int lhi = lane >> 4;
    uint32_t aoff[2];
    #pragma unroll
    for (int mf = 0; mf < 2; ++mf)
        aoff[mf] = (uint32_t)((m0 + mf * 16 + l15) * (LDK * 4) + lhi * 16);

    float acc[2][8][4];
    #pragma unroll
    for (int mf = 0; mf < 2; ++mf)
        #pragma unroll
        for (int nf = 0; nf < 8; ++nf)
            #pragma unroll
            for (int i = 0; i < 4; ++i) acc[mf][nf][i] = 0.0f;

    issue_stage(0); CP_COMMIT();
    issue_stage(1); CP_COMMIT();

    for (int kt = 0; kt < NK; ++kt) {
        CP_WAIT(1);                      // stage kt resident (kt+1 may be in flight)
        __syncthreads();                 // readers of buffer (kt+2)%3 (iter kt-1) done

        if (kt + 2 < NK) { issue_stage(kt + 2); CP_COMMIT(); }

        const uint32_t stg = sBase + (uint32_t)((kt % NSTAGE) * STG_BYTES);
        const uint32_t bB  = stg + A_BYTES;

        #pragma unroll
        for (int q = 0; q < 2; ++q) {
            uint32_t af[2][4];
            #pragma unroll
            for (int mf = 0; mf < 2; ++mf) {
                LDSM4(af[mf], stg + aoff[mf] + q * 32);
                af[mf][0] = f2tf32(af[mf][0]); af[mf][1] = f2tf32(af[mf][1]);
                af[mf][2] = f2tf32(af[mf][2]); af[mf][3] = f2tf32(af[mf][3]);
            }
            #pragma unroll
            for (int nf = 0; nf < 8; ++nf) {
                const uint32_t c = (uint32_t)(n0 + nf * 8 + tg) * 4;
                uint32_t v0, v1;
                asm volatile("ld.shared.b32 %0, [%1];" : "=r"(v0)
                             : "r"(bB + (uint32_t)((q * 8 + tig) * LDBN) * 4 + c));
                asm volatile("ld.shared.b32 %0, [%1];" : "=r"(v1)
                             : "r"(bB + (uint32_t)((q * 8 + 4 + tig) * LDBN) * 4 + c));
                v0 = f2tf32(v0);
                v1 = f2tf32(v1);
                mma_tf32(acc[0][nf], af[0], v0, v1);
                mma_tf32(acc[1][nf], af[1], v0, v1);
            }
        }
    }

    // ---- epilogue: predicated float2 stores ----
    #pragma unroll
    for (int mf = 0; mf < 2; ++mf) {
        const int r0 = mt * BM + m0 + mf * 16 + tg;
        const int r1 = r0 + 8;
        #pragma unroll
        for (int nf = 0; nf < 8; ++nf) {
            const int col = nt * BN + n0 + nf * 8 + tig * 2;
            if (col < DOUT_) {
                if (r0 < cnt) {
                    float2 v = make_float2(acc[mf][nf][0], acc[mf][nf][1]);
                    *(float2*)&Y[(long long)(gstart + r0) * DOUT_ + col] = v;
                }
                if (r1 < cnt) {
                    float2 v = make_float2(acc[mf][nf][2], acc[mf][nf][3]);
                    *(float2*)&Y[(long long)(gstart + r1) * DOUT_ + col] = v;
                }
            }
        }
    }
}

extern "C" void kernel_launch(void* const* d_in, const int* in_sizes, int n_in,
                              void* d_out, int out_size) {
    const float* x    = (const float*)d_in[0];
    const float* w    = (const float*)d_in[1];
    const int*   cnts = (const int*)d_in[2];
    float* y = (float*)d_out;

    starts_kernel<<<1, 32>>>(cnts);

    cudaFuncSetAttribute(grouped_gemm_kernel,
                         cudaFuncAttributeMaxDynamicSharedMemorySize, SMEM_TOTAL);
    dim3 grid(NT_N, CAP_ / BM, G_);      // (7, 4, 64)
    grouped_gemm_kernel<<<grid, 256, SMEM_TOTAL>>>(x, w, cnts, y);
}